// round 2
// baseline (speedup 1.0000x reference)
#include <cuda_runtime.h>

// Problem shape (fixed by setup_inputs)
#define BB 8
#define NN 2000
#define EE 20
#define HH 128
#define ROWS (BB * NN)      // 16000 node rows
#define EROWS (BB * NN * EE) // 320000 edge rows

// Scratch for the two small linears (16.4 MB total) — static device arrays,
// no allocation at runtime.
__device__ float g_Ux[ROWS * HH];
__device__ float g_Vx[ROWS * HH];

// -----------------------------------------------------------------------------
// linear_kernel: out[r][h] = sum_k x[r][k] * W[k][h] + bias[h]
// which==0 -> g_Ux, which==1 -> g_Vx
// Block: 256 threads, 32 rows per block. Thread tile: 4 rows x 4 h (float4).
// x tile in smem (warp-broadcast reads); W streamed via L1 (64KB, stays hot).
// -----------------------------------------------------------------------------
__global__ __launch_bounds__(256) void linear_kernel(
    const float* __restrict__ x,
    const float* __restrict__ W,
    const float* __restrict__ bias,
    int which)
{
    __shared__ float x_s[32 * HH];  // 16 KB

    const int t   = threadIdx.x;      // 0..255
    const int hq  = t & 31;           // h quad: columns hq*4 .. hq*4+3
    const int rg  = t >> 5;           // 0..7 : rows rg*4 .. rg*4+3
    const int row0 = blockIdx.x * 32;

    // Cooperative load of the 32x128 x tile (1024 float4)
    {
        const float4* xg = (const float4*)(x + (size_t)row0 * HH);
        float4* xs4 = (float4*)x_s;
        #pragma unroll
        for (int i = 0; i < 4; i++) xs4[t + i * 256] = xg[t + i * 256];
    }
    __syncthreads();

    float acc[4][4];
    #pragma unroll
    for (int r = 0; r < 4; r++)
        #pragma unroll
        for (int j = 0; j < 4; j++) acc[r][j] = 0.f;

    #pragma unroll 4
    for (int k = 0; k < HH; k++) {
        const float4 w4 = *(const float4*)(W + (size_t)k * HH + hq * 4);
        #pragma unroll
        for (int r = 0; r < 4; r++) {
            const float xv = x_s[(rg * 4 + r) * HH + k];  // warp-uniform broadcast
            acc[r][0] += xv * w4.x;
            acc[r][1] += xv * w4.y;
            acc[r][2] += xv * w4.z;
            acc[r][3] += xv * w4.w;
        }
    }

    float* out = which ? g_Vx : g_Ux;
    const float4 b4 = *(const float4*)(bias + hq * 4);
    #pragma unroll
    for (int r = 0; r < 4; r++) {
        float4 o;
        o.x = acc[r][0] + b4.x;
        o.y = acc[r][1] + b4.y;
        o.z = acc[r][2] + b4.z;
        o.w = acc[r][3] + b4.w;
        *(float4*)(out + (size_t)(row0 + rg * 4 + r) * HH + hq * 4) = o;
    }
}

// -----------------------------------------------------------------------------
// fused_kernel: one CTA per node (grid = 16000), 128 threads (thread = channel h).
//   1. Load the node's 20 contiguous edge rows [20x128] into smem.
//   2. ve[e] = dot(e_row[e], We[:,h])   (be dropped: softmax is shift-invariant)
//   3. per-thread softmax over the 20 values
//   4. acc = sum_e p[e] * Vx[b, idx[e], h]   (gathers hit L2: Vx is 8.2 MB)
//   5. out = Ux + acc
// -----------------------------------------------------------------------------
__global__ __launch_bounds__(128) void fused_kernel(
    const float* __restrict__ e,
    const float* __restrict__ We,
    const int* __restrict__ edge_index,
    float* __restrict__ out)
{
    __shared__ float e_s[EE * HH];  // 10 KB
    __shared__ int   idx_s[EE];

    const int t   = threadIdx.x;   // channel h
    const int row = blockIdx.x;    // 0..15999
    const int b   = row / NN;
    const int n   = row - b * NN;

    // 20 edge rows for (b,n) are contiguous: 2560 floats = 640 float4
    {
        const float4* eg = (const float4*)(e + ((size_t)b * NN * EE + (size_t)n * EE) * HH);
        float4* es4 = (float4*)e_s;
        #pragma unroll
        for (int i = 0; i < 5; i++) es4[t + i * 128] = eg[t + i * 128];
    }
    if (t < EE) idx_s[t] = edge_index[(size_t)b * NN * EE + (size_t)n * EE + t];
    __syncthreads();

    float ve[EE];
    #pragma unroll
    for (int i = 0; i < EE; i++) ve[i] = 0.f;

    #pragma unroll 4
    for (int k = 0; k < HH; k++) {
        const float w = We[(size_t)k * HH + t];  // one 128B sector/warp/k, L1-hot
        #pragma unroll
        for (int i = 0; i < EE; i++) ve[i] += e_s[i * HH + k] * w;
    }

    // softmax over the E axis (pure per-thread register math)
    float m = ve[0];
    #pragma unroll
    for (int i = 1; i < EE; i++) m = fmaxf(m, ve[i]);
    float s = 0.f;
    #pragma unroll
    for (int i = 0; i < EE; i++) { ve[i] = __expf(ve[i] - m); s += ve[i]; }
    const float inv = 1.f / s;

    // gather + weighted sum
    float acc = 0.f;
    #pragma unroll
    for (int i = 0; i < EE; i++) {
        acc += ve[i] * g_Vx[((size_t)b * NN + idx_s[i]) * HH + t];
    }

    out[(size_t)row * HH + t] = g_Ux[(size_t)row * HH + t] + acc * inv;
}

// -----------------------------------------------------------------------------
// Launch
// Inputs (metadata order): x, e, Wu, bu, Wv, bv, We, be, edge_index, n_edges
// -----------------------------------------------------------------------------
extern "C" void kernel_launch(void* const* d_in, const int* in_sizes, int n_in,
                              void* d_out, int out_size)
{
    const float* x   = (const float*)d_in[0];
    const float* e   = (const float*)d_in[1];
    const float* Wu  = (const float*)d_in[2];
    const float* bu  = (const float*)d_in[3];
    const float* Wv  = (const float*)d_in[4];
    const float* bv  = (const float*)d_in[5];
    const float* We  = (const float*)d_in[6];
    // be (d_in[7]) is mathematically irrelevant: softmax over E is invariant
    // to per-(n,h) constant shifts.
    const int* edge_index = (const int*)d_in[8];
    float* out = (float*)d_out;

    (void)in_sizes; (void)n_in; (void)out_size;

    linear_kernel<<<ROWS / 32, 256>>>(x, Wu, bu, /*which=*/0);  // Ux
    linear_kernel<<<ROWS / 32, 256>>>(x, Wv, bv, /*which=*/1);  // Vx
    fused_kernel<<<ROWS, 128>>>(e, We, edge_index, out);
}